// round 7
// baseline (speedup 1.0000x reference)
#include <cuda_runtime.h>
#include <math.h>

#define N        96
#define NB       32      // blocks; block b owns rows 3b..3b+2
#define NT       288     // threads per block (9 warps)
#define NN       9216
#define IN_DIM   64
#define HID      256
#define ZD       64
#define E        1024
#define NUM_LOGITS 4656
#define ITERS    50
#define UTRI     4560    // N*(N-1)/2

// ---------------- device scratch (no allocations allowed) ----------------
__device__ float g_Anorm[NN];
__device__ float g_T[N * HID];
__device__ float g_P[N * HID];
__device__ float g_H[N * HID];
__device__ float g_gv[HID];
__device__ float g_B[NN];
__device__ float g_degA[N];
__device__ int   g_deg[N];
__device__ int   g_nbr[NN];
__device__ float g_M[2][NN];          // cross-block double buffer
__device__ float g_part[2][NB];       // per-block sum-of-squares partials (dbl-buf)
__device__ unsigned g_flag[NB];       // per-block monotone phase flags (zero-init)

__global__ void __launch_bounds__(NT, 1) fused_graphvae(
    const float* __restrict__ x,   const int* __restrict__ ei,
    const float* __restrict__ adj,
    const float* __restrict__ W1,  const float* __restrict__ g1,  const float* __restrict__ be1,
    const float* __restrict__ W2,  const float* __restrict__ g2,  const float* __restrict__ be2,
    const float* __restrict__ Wmu, const float* __restrict__ bmu,
    const float* __restrict__ Wlv, const float* __restrict__ blv,
    const float* __restrict__ Wd1, const float* __restrict__ bd1,
    const float* __restrict__ Wd2, const float* __restrict__ bd2,
    const float* __restrict__ eps, float* __restrict__ out)
{
    __shared__ float dyn[NN];          // 36 KB: adjacency / staging / B' in MPM
    __shared__ float sX[3 * N];        // block's 3 X rows
    __shared__ float sND[3 * N];       // block's 3 nd rows
    __shared__ int   snbr[3 * N];      // neighbor lists for the 3 rows
    __shared__ int   sdeg[3];
    __shared__ float spart[9 * N];     // [chunk][row][k] partial maxes / temps
    __shared__ float red[16];
    __shared__ float s_scale;
    __shared__ unsigned s_base;

    const int t    = threadIdx.x;            // 0..287
    const int bid  = blockIdx.x;             // 0..31
    const int lane = t & 31, wid = t >> 5;
    const int r    = t / 96;                 // row-in-block AND chunk id (0..2)
    const int k    = t - r * 96;             // column 0..95
    const int grow = 3 * bid + r;            // global row

    // Per-launch flag base: only this block ever writes g_flag[bid], and all
    // flags are equal at launch start (each block publishes the same count).
    if (t == 0) s_base = __ldcg(&g_flag[bid]);
    __syncthreads();

    // Decentralized release: every thread fences its own st.cg writes, then
    // thread 0 publishes the block's phase flag (CG grid-sync pattern).
    auto publish = [&](unsigned phv) {
        __threadfence();
        __syncthreads();
        if (t == 0) __stcg(&g_flag[bid], s_base + phv);
    };
    // Wait until ALL blocks have published >= phv. Warp 0 polls the 32-flag
    // cache line with acquire loads; one L2 round trip per poll.
    auto wait_all = [&](unsigned phv) {
        if (wid == 0) {
            const unsigned* fp = &g_flag[lane];
            unsigned tgt = phv;
            bool ok;
            do {
                unsigned v;
                asm volatile("ld.acquire.gpu.u32 %0, [%1];" : "=r"(v) : "l"(fp) : "memory");
                ok = ((int)(v - s_base) >= (int)tgt);
            } while (__ballot_sync(~0u, ok) != ~0u);
        }
        __syncthreads();
    };

    // ============ Ph1: adjacency (block 0) + gemm1 (blocks 1..31) ==========
    if (bid == 0) {
        for (int i = t; i < NN; i += NT) dyn[i] = 0.f;
        __syncthreads();
        for (int e = t; e < E; e += NT) {
            int s = ei[e], d = ei[E + e];
            dyn[s * N + d] = 1.f;                 // identical-value races: benign
        }
        __syncthreads();
        if (t < N) dyn[t * (N + 1)] = 1.f;        // A = max(A, I)
        __syncthreads();
        for (int row = wid; row < N; row += 9) {  // warp-per-row sum
            float s = dyn[row * N + lane] + dyn[row * N + lane + 32]
                    + dyn[row * N + lane + 64];
            #pragma unroll
            for (int o = 16; o > 0; o >>= 1) s += __shfl_xor_sync(~0u, s, o);
            if (lane == 0) spart[row] = rsqrtf(s);
        }
        __syncthreads();
        for (int i = t; i < NN; i += NT) {
            int rr = i / N, cc = i - rr * N;
            __stcg(&g_Anorm[i], dyn[i] * spart[rr] * spart[cc]);
        }
        if (t < N) {
            float s = 0.f; int cnt = 0;
            for (int j = 0; j < N; j++) {
                float v = adj[t * N + j];
                s += v;
                if (v > 0.5f) __stcg(&g_nbr[t * N + cnt++], j);
            }
            __stcg(&g_degA[t], s + 1.f);          // Agt diag forced to 1
            __stcg(&g_deg[t], cnt);
        }
    } else {
        // T = x @ W1 (bias b1 exactly cancelled by BN)
        for (int i = t; i < N * IN_DIM; i += NT) dyn[i] = x[i];
        __syncthreads();
        for (int o = (bid - 1) * NT + t; o < N * HID; o += (NB - 1) * NT) {
            int i = o >> 8, c = o & 255;
            float acc = 0.f;
            #pragma unroll
            for (int kk = 0; kk < IN_DIM; kk++)
                acc += dyn[i * IN_DIM + kk] * W1[kk * HID + c];
            __stcg(&g_T[o], acc);
        }
    }
    publish(1);

    // ============ gcn: P = A_norm @ T (3 rows per block) ====================
    auto gcn = [&]() {
        dyn[t] = __ldcg(&g_Anorm[grow * N + k]);   // stage 3 A_norm rows
        __syncthreads();
        for (int o = t; o < 3 * HID; o += NT) {
            int rr = o >> 8, c = o & 255;
            float acc = 0.f;
            #pragma unroll 4
            for (int j = 0; j < N; j++)
                acc += dyn[rr * N + j] * __ldcg(&g_T[j * HID + c]);
            __stcg(&g_P[(3 * bid + rr) * HID + c], acc);
        }
    };
    // ============ bn: BN + relu, warp-per-column ============================
    auto bn = [&](const float* gamma, const float* beta, int write_h, int do_gv) {
        if (wid < 8) {
            int c = bid * 8 + wid;
            float v0 = __ldcg(&g_P[lane * HID + c]);
            float v1 = __ldcg(&g_P[(lane + 32) * HID + c]);
            float v2 = __ldcg(&g_P[(lane + 64) * HID + c]);
            float s = v0 + v1 + v2;
            float q = v0 * v0 + v1 * v1 + v2 * v2;
            #pragma unroll
            for (int o = 16; o > 0; o >>= 1) {
                s += __shfl_xor_sync(~0u, s, o);
                q += __shfl_xor_sync(~0u, q, o);
            }
            float m   = s * (1.f / N);
            float var = q * (1.f / N) - m * m;
            float inv = rsqrtf(var + 1e-5f) * gamma[c];
            float bb  = beta[c];
            float h0 = fmaxf((v0 - m) * inv + bb, 0.f);
            float h1 = fmaxf((v1 - m) * inv + bb, 0.f);
            float h2 = fmaxf((v2 - m) * inv + bb, 0.f);
            if (write_h) {
                __stcg(&g_H[lane * HID + c], h0);
                __stcg(&g_H[(lane + 32) * HID + c], h1);
                __stcg(&g_H[(lane + 64) * HID + c], h2);
            }
            if (do_gv) {
                float gs = h0 + h1 + h2;
                #pragma unroll
                for (int o = 16; o > 0; o >>= 1) gs += __shfl_xor_sync(~0u, gs, o);
                if (lane == 0) __stcg(&g_gv[c], gs * (1.f / N));
            }
        }
    };

    wait_all(1); gcn();              publish(2);
    wait_all(2); bn(g1, be1, 1, 0);  publish(3);

    // ============ Ph4: T = H @ W2 ==========================================
    wait_all(3);
    {
        for (int o = t; o < 3 * HID; o += NT)
            dyn[o] = __ldcg(&g_H[(3 * bid + (o >> 8)) * HID + (o & 255)]);
        __syncthreads();
        for (int o = t; o < 3 * HID; o += NT) {
            int rr = o >> 8, c = o & 255;
            float acc = 0.f;
            #pragma unroll 4
            for (int kk = 0; kk < HID; kk++)
                acc += dyn[rr * HID + kk] * W2[kk * HID + c];
            __stcg(&g_T[(3 * bid + rr) * HID + c], acc);
        }
    }
    publish(4);
    wait_all(4); gcn();              publish(5);
    wait_all(5); bn(g2, be2, 0, 1);  publish(6);   // bn2: only g_vec needed

    // ============ Ph7: head (replicated per block) + decoder -> B ===========
    wait_all(6);
    {
        // z and d1 computed redundantly in every block (tiny) — no extra phase
        if (t < HID) dyn[t] = __ldcg(&g_gv[t]);
        __syncthreads();
        if (t < ZD) {
            float mu = bmu[t], lv = blv[t];
            #pragma unroll 4
            for (int kk = 0; kk < HID; kk++) {
                float g = dyn[kk];
                mu += g * Wmu[kk * ZD + t];
                lv += g * Wlv[kk * ZD + t];
            }
            lv = fminf(fmaxf(lv, -4.f), 4.f);
            dyn[HID + t] = mu + eps[t] * expf(0.5f * lv);
        }
        __syncthreads();
        if (t < HID) {
            float acc = bd1[t];
            #pragma unroll
            for (int d = 0; d < ZD; d++) acc += dyn[HID + d] * Wd1[d * HID + t];
            dyn[HID + ZD + t] = fmaxf(acc, 0.f);   // d1 in shared
        }
        __syncthreads();
        int u = bid * NT + t;                      // one upper-tri entry per thread
        if (u < UTRI) {
            int uu = u, rr = 0, rem = N - 1;
            while (uu >= rem) { uu -= rem; rem--; rr++; }
            int cc = rr + 1 + uu;
            float acc = bd2[u];
            #pragma unroll 4
            for (int kk = 0; kk < HID; kk++)
                acc += dyn[HID + ZD + kk] * Wd2[kk * NUM_LOGITS + u];
            float th  = tanhf(acc);
            float sig = 1.f / (1.f + expf(-th));
            __stcg(&g_B[rr * N + cc], sig);
            __stcg(&g_B[cc * N + rr], sig);
        }
        if (bid == 16 && t < N) __stcg(&g_B[t * (N + 1)], 1.f);  // diag = 1
    }
    publish(7);

    // ============ Ph8: prep — B' (diag zeroed) in shared, nd, X0, M0 ========
    wait_all(7);
    {
        for (int i = t; i < NN; i += NT) {
            int rr = i / N, cc = i - rr * N;
            dyn[i] = (rr == cc) ? 0.f : __ldcg(&g_B[i]);
        }
        __syncthreads();
        if (t < N) {                   // column stats (B symmetric): conflict-free
            float db = 1.f, mx = 0.f;
            #pragma unroll 4
            for (int l = 0; l < N; l++) {
                float b = dyn[l * N + t];
                db += b;
                mx = fmaxf(mx, b);
            }
            spart[t] = db;
            float m0 = mx * (1.f / N);             // X0 uniform, ||X0||_F = 1
            __stcg(&g_M[0][(3 * bid + 0) * N + t], m0);
            __stcg(&g_M[0][(3 * bid + 1) * N + t], m0);
            __stcg(&g_M[0][(3 * bid + 2) * N + t], m0);
        }
        __syncthreads();
        sND[t]  = 1.f / (fabsf(__ldcg(&g_degA[grow]) - spart[k]) + 1.f);
        sX[t]   = 1.f / N;
        snbr[t] = __ldcg(&g_nbr[grow * N + k]);
        if (t < 3) sdeg[t] = __ldcg(&g_deg[3 * bid + t]);
        __syncthreads();
    }
    publish(8);

    const int myDeg = sdeg[r];
    const int* myNbr = &snbr[r * N];

    // ============ 50 MPM iterations, one flag round each ====================
    // Exact per-step normalization: F is positively homogeneous, so the input
    // pre-scale rsqrt(||X_t||^2) (partials published with the SAME release as
    // the M rows) reproduces the reference's output normalization exactly.
    for (int it = 0; it < ITERS; it++) {
        wait_all(8 + it);
        const float* __restrict__ Min  = g_M[it & 1];
        float*       __restrict__ Mout = g_M[(it + 1) & 1];

        if (it == 0) { if (t == 0) s_scale = 1.f; }
        else if (wid == 0) {
            float p = __ldcg(&g_part[(it - 1) & 1][lane]);   // NB == 32 partials
            #pragma unroll
            for (int o = 16; o > 0; o >>= 1) p += __shfl_xor_sync(~0u, p, o);
            if (lane == 0) s_scale = rsqrtf(p);
        }

        float acc = sX[t] * sND[t];
        #pragma unroll 4
        for (int m = 0; m < myDeg; m++) acc += __ldcg(&Min[myNbr[m] * N + k]);
        __syncthreads();                          // s_scale ready
        acc *= s_scale;
        sX[t] = acc;

        float sq = acc * acc;
        #pragma unroll
        for (int o = 16; o > 0; o >>= 1) sq += __shfl_xor_sync(~0u, sq, o);
        if (lane == 0) red[wid] = sq;
        __syncthreads();                          // also publishes sX block-wide
        if (t == 0) {
            float s = 0.f;
            #pragma unroll
            for (int w = 0; w < 9; w++) s += red[w];
            __stcg(&g_part[it & 1][bid], s);
        }

        if (it != ITERS - 1) {
            // M[row,k] = max_{l != k} B[k,l] * x_row[l]
            // thread (chunk=r, k): 32 l's, all 3 rows share the B read.
            const int lbase = r * 32;
            float mx0 = 0.f, mx1 = 0.f, mx2 = 0.f;
            #pragma unroll 8
            for (int ll = 0; ll < 32; ll++) {
                float b = dyn[(lbase + ll) * N + k];   // diag zeroed -> l!=k free
                mx0 = fmaxf(mx0, b * sX[lbase + ll]);
                mx1 = fmaxf(mx1, b * sX[96 + lbase + ll]);
                mx2 = fmaxf(mx2, b * sX[192 + lbase + ll]);
            }
            spart[(r * 3 + 0) * N + k] = mx0;
            spart[(r * 3 + 1) * N + k] = mx1;
            spart[(r * 3 + 2) * N + k] = mx2;
            __syncthreads();
            float mm = fmaxf(fmaxf(spart[(0 * 3 + r) * N + k],
                                   spart[(1 * 3 + r) * N + k]),
                                   spart[(2 * 3 + r) * N + k]);
            __stcg(&Mout[grow * N + k], mm);
        }
        publish(9 + it);
    }

    // ============ final normalize + write ==================================
    wait_all(9 + ITERS - 1);
    {
        if (wid == 0) {
            float p = __ldcg(&g_part[(ITERS - 1) & 1][lane]);
            #pragma unroll
            for (int o = 16; o > 0; o >>= 1) p += __shfl_xor_sync(~0u, p, o);
            if (lane == 0) s_scale = rsqrtf(p);
        }
        __syncthreads();
        out[grow * N + k] = sX[t] * s_scale;
    }
}

// ---------------- launch ----------------
extern "C" void kernel_launch(void* const* d_in, const int* in_sizes, int n_in,
                              void* d_out, int out_size) {
    const float* x   = (const float*)d_in[0];
    const int*   ei  = (const int*)  d_in[1];
    const float* adj = (const float*)d_in[2];
    const float* W1  = (const float*)d_in[3];
    // d_in[4] = b1 (cancelled by BN)
    const float* g1  = (const float*)d_in[5];
    const float* be1 = (const float*)d_in[6];
    const float* W2  = (const float*)d_in[7];
    // d_in[8] = b2 (cancelled by BN)
    const float* g2  = (const float*)d_in[9];
    const float* be2 = (const float*)d_in[10];
    const float* Wmu = (const float*)d_in[11];
    const float* bmu = (const float*)d_in[12];
    const float* Wlv = (const float*)d_in[13];
    const float* blv = (const float*)d_in[14];
    const float* Wd1 = (const float*)d_in[15];
    const float* bd1 = (const float*)d_in[16];
    const float* Wd2 = (const float*)d_in[17];
    const float* bd2 = (const float*)d_in[18];
    const float* eps = (const float*)d_in[19];

    fused_graphvae<<<NB, NT>>>(
        x, ei, adj, W1, g1, be1, W2, g2, be2,
        Wmu, bmu, Wlv, blv, Wd1, bd1, Wd2, bd2, eps, (float*)d_out);
}

// round 8
// speedup vs baseline: 1.0551x; 1.0551x over previous
#include <cuda_runtime.h>
#include <math.h>

#define N        96
#define NB       8       // one cluster of 8 CTAs; CTA b owns rows 12b..12b+11
#define NT       384     // 12 warps
#define RPB      12      // rows per block
#define NN       9216
#define IN_DIM   64
#define HID      256
#define ZD       64
#define E        1024
#define NUM_LOGITS 4656
#define ITERS    50
#define UTRI     4560

// ---------------- device scratch (no allocations allowed) ----------------
__device__ float g_Anorm[NN];
__device__ float g_T[N * HID];
__device__ float g_P[N * HID];
__device__ float g_H[N * HID];
__device__ float g_gv[HID];
__device__ float g_B[NN];
__device__ float g_degA[N];
__device__ int   g_deg[N];
__device__ int   g_nbr[NN];
__device__ float g_M[2][NN];          // cross-CTA double buffer
__device__ float g_part[2][NB];       // per-CTA sum-of-squares partials

// Cluster-wide barrier: ~380 cyc, release/acquire semantics, subsumes
// __syncthreads (wait completes only after every warp of every CTA arrived).
#define CSYNC() do { \
    asm volatile("barrier.cluster.arrive.aligned;" ::: "memory"); \
    asm volatile("barrier.cluster.wait.aligned;"   ::: "memory"); \
} while (0)

__global__ void __launch_bounds__(NT, 1) __cluster_dims__(NB, 1, 1)
fused_graphvae(
    const float* __restrict__ x,   const int* __restrict__ ei,
    const float* __restrict__ adj,
    const float* __restrict__ W1,  const float* __restrict__ g1,  const float* __restrict__ be1,
    const float* __restrict__ W2,  const float* __restrict__ g2,  const float* __restrict__ be2,
    const float* __restrict__ Wmu, const float* __restrict__ bmu,
    const float* __restrict__ Wlv, const float* __restrict__ blv,
    const float* __restrict__ Wd1, const float* __restrict__ bd1,
    const float* __restrict__ Wd2, const float* __restrict__ bd2,
    const float* __restrict__ eps, float* __restrict__ out)
{
    __shared__ float dyn[NN];              // 36 KB: adjacency / staging / B'
    __shared__ float sX[RPB * N];          // this CTA's 12 X rows
    __shared__ float sND[RPB * N];         // this CTA's 12 nd rows
    __shared__ unsigned char snbr[RPB * N];// neighbor ids (< 96) for 12 rows
    __shared__ float sdb[N];               // degB per column (prep)
    __shared__ int   sdeg[RPB];
    __shared__ float red[12];
    __shared__ float s_scale;

    const int t    = threadIdx.x;          // 0..383
    const int bid  = blockIdx.x;           // 0..7
    const int lane = t & 31, wid = t >> 5;
    const int kk   = t % 96;               // column
    const int row0 = t / 96;               // 0..3

    // ============ Ph1: adjacency (CTA 0) + gemm1 (CTAs 1..7) ===============
    if (bid == 0) {
        for (int i = t; i < NN; i += NT) dyn[i] = 0.f;
        __syncthreads();
        for (int e = t; e < E; e += NT)
            dyn[ei[e] * N + ei[E + e]] = 1.f;      // identical-value races OK
        __syncthreads();
        if (t < N) dyn[t * (N + 1)] = 1.f;         // A = max(A, I)
        __syncthreads();
        for (int rr = wid; rr < N; rr += 12) {     // warp-per-row sums
            float s = dyn[rr * N + lane] + dyn[rr * N + lane + 32]
                    + dyn[rr * N + lane + 64];
            #pragma unroll
            for (int o = 16; o; o >>= 1) s += __shfl_xor_sync(~0u, s, o);
            if (lane == 0) sX[rr] = rsqrtf(s);     // sX as temp dinv
        }
        __syncthreads();
        for (int i = t; i < NN; i += NT) {
            int rr = i / N, cc = i - rr * N;
            __stcg(&g_Anorm[i], dyn[i] * sX[rr] * sX[cc]);
        }
        if (t < N) {
            float s = 0.f; int cnt = 0;
            for (int j = 0; j < N; j++) {
                float v = adj[t * N + j];
                s += v;
                if (v > 0.5f) __stcg(&g_nbr[t * N + cnt++], j);
            }
            __stcg(&g_degA[t], s + 1.f);           // Agt diag forced to 1
            __stcg(&g_deg[t], cnt);
        }
    } else {
        // T = x @ W1 (bias b1 exactly cancelled by BN); float4 over columns
        for (int e = t; e < N * IN_DIM; e += NT) dyn[e] = x[e];
        __syncthreads();
        for (int q = (bid - 1) * NT + t; q < N * (HID / 4); q += 7 * NT) {
            int i = q >> 6, c4 = (q & 63) << 2;
            float a0 = 0, a1 = 0, a2 = 0, a3 = 0;
            #pragma unroll
            for (int k2 = 0; k2 < IN_DIM; k2++) {
                float xv = dyn[i * IN_DIM + k2];
                float4 w = *(const float4*)&W1[k2 * HID + c4];
                a0 += xv * w.x; a1 += xv * w.y; a2 += xv * w.z; a3 += xv * w.w;
            }
            __stcg((float4*)&g_T[i * HID + c4], make_float4(a0, a1, a2, a3));
        }
    }
    CSYNC();

    // ============ gcn: P = A_norm @ T (12 rows per CTA) =====================
    auto gcn = [&]() {
        for (int e = t; e < RPB * N; e += NT)
            dyn[e] = __ldcg(&g_Anorm[bid * RPB * N + e]);
        __syncthreads();
        for (int q = t; q < RPB * (HID / 4); q += NT) {   // 2 quads per thread
            int rr = q >> 6, c4 = (q & 63) << 2;
            float a0 = 0, a1 = 0, a2 = 0, a3 = 0;
            #pragma unroll 4
            for (int j = 0; j < N; j++) {
                float av = dyn[rr * N + j];
                float4 tv = __ldcg((const float4*)&g_T[j * HID + c4]);
                a0 += av * tv.x; a1 += av * tv.y; a2 += av * tv.z; a3 += av * tv.w;
            }
            __stcg((float4*)&g_P[(bid * RPB + rr) * HID + c4],
                   make_float4(a0, a1, a2, a3));
        }
    };
    // ============ bn: BN + relu, warp-per-column (32 cols per CTA) ==========
    auto bn = [&](const float* gamma, const float* beta, int write_h, int do_gv) {
        for (int cc = wid; cc < 32; cc += 12) {
            int c = bid * 32 + cc;
            float v0 = __ldcg(&g_P[lane * HID + c]);
            float v1 = __ldcg(&g_P[(lane + 32) * HID + c]);
            float v2 = __ldcg(&g_P[(lane + 64) * HID + c]);
            float s = v0 + v1 + v2;
            float q = v0 * v0 + v1 * v1 + v2 * v2;
            #pragma unroll
            for (int o = 16; o; o >>= 1) {
                s += __shfl_xor_sync(~0u, s, o);
                q += __shfl_xor_sync(~0u, q, o);
            }
            float m   = s * (1.f / N);
            float var = q * (1.f / N) - m * m;
            float inv = rsqrtf(var + 1e-5f) * gamma[c];
            float bb  = beta[c];
            float h0 = fmaxf((v0 - m) * inv + bb, 0.f);
            float h1 = fmaxf((v1 - m) * inv + bb, 0.f);
            float h2 = fmaxf((v2 - m) * inv + bb, 0.f);
            if (write_h) {
                __stcg(&g_H[lane * HID + c], h0);
                __stcg(&g_H[(lane + 32) * HID + c], h1);
                __stcg(&g_H[(lane + 64) * HID + c], h2);
            }
            if (do_gv) {
                float gs = h0 + h1 + h2;
                #pragma unroll
                for (int o = 16; o; o >>= 1) gs += __shfl_xor_sync(~0u, gs, o);
                if (lane == 0) __stcg(&g_gv[c], gs * (1.f / N));
            }
        }
    };

    gcn();             CSYNC();
    bn(g1, be1, 1, 0); CSYNC();

    // ============ gemm2: T = H @ W2 =========================================
    {
        for (int e = t; e < RPB * HID; e += NT)
            dyn[e] = __ldcg(&g_H[bid * RPB * HID + e]);
        __syncthreads();
        for (int q = t; q < RPB * (HID / 4); q += NT) {
            int rr = q >> 6, c4 = (q & 63) << 2;
            float a0 = 0, a1 = 0, a2 = 0, a3 = 0;
            #pragma unroll 4
            for (int k2 = 0; k2 < HID; k2++) {
                float hv = dyn[rr * HID + k2];
                float4 w = *(const float4*)&W2[k2 * HID + c4];
                a0 += hv * w.x; a1 += hv * w.y; a2 += hv * w.z; a3 += hv * w.w;
            }
            __stcg((float4*)&g_T[(bid * RPB + rr) * HID + c4],
                   make_float4(a0, a1, a2, a3));
        }
    }
    CSYNC();
    gcn();             CSYNC();
    bn(g2, be2, 0, 1); CSYNC();          // bn2: only g_vec needed

    // ============ head (replicated per CTA) + decoder -> B ==================
    {
        if (t < HID) dyn[t] = __ldcg(&g_gv[t]);
        __syncthreads();
        if (t < ZD) {
            float mu = bmu[t], lv = blv[t];
            #pragma unroll 4
            for (int k2 = 0; k2 < HID; k2++) {
                float g = dyn[k2];
                mu += g * Wmu[k2 * ZD + t];
                lv += g * Wlv[k2 * ZD + t];
            }
            lv = fminf(fmaxf(lv, -4.f), 4.f);
            dyn[HID + t] = mu + eps[t] * expf(0.5f * lv);
        }
        __syncthreads();
        if (t < HID) {
            float a = bd1[t];
            #pragma unroll
            for (int d = 0; d < ZD; d++) a += dyn[HID + d] * Wd1[d * HID + t];
            dyn[HID + ZD + t] = fmaxf(a, 0.f);     // d1
        }
        __syncthreads();
        for (int u = bid * NT + t; u < UTRI; u += NB * NT) {
            int uu = u, rr = 0, rem = N - 1;
            while (uu >= rem) { uu -= rem; rem--; rr++; }
            int cc = rr + 1 + uu;
            float a = bd2[u];
            #pragma unroll 4
            for (int k2 = 0; k2 < HID; k2++)
                a += dyn[HID + ZD + k2] * Wd2[k2 * NUM_LOGITS + u];
            float th  = tanhf(a);
            float sig = 1.f / (1.f + expf(-th));
            __stcg(&g_B[rr * N + cc], sig);
            __stcg(&g_B[cc * N + rr], sig);
        }
        if (bid == 0 && t < N) __stcg(&g_B[t * (N + 1)], 1.f);   // diag = 1
    }
    CSYNC();

    // ============ prep: B' (diag zeroed) in shared, nd, X0, M0 ==============
    {
        for (int i = t; i < NN; i += NT) {
            int rr = i / N, cc = i - rr * N;
            dyn[i] = (rr == cc) ? 0.f : __ldcg(&g_B[i]);
        }
        __syncthreads();
        if (t < N) {                  // column stats (B symmetric): conflict-free
            float db = 1.f, mx = 0.f;
            #pragma unroll 4
            for (int l = 0; l < N; l++) {
                float b = dyn[l * N + t];
                db += b;
                mx = fmaxf(mx, b);
            }
            sdb[t] = db;
            float m0 = mx * (1.f / N);            // X0 uniform, ||X0||_F = 1
            for (int r2 = 0; r2 < RPB; r2++)
                __stcg(&g_M[0][(bid * RPB + r2) * N + t], m0);
        }
        __syncthreads();
        #pragma unroll
        for (int i2 = 0; i2 < 3; i2++) {
            int e  = t + i2 * NT;
            int rw = row0 + i2 * 4;
            sND[e]  = 1.f / (fabsf(__ldcg(&g_degA[bid * RPB + rw]) - sdb[kk]) + 1.f);
            sX[e]   = 1.f / N;
            snbr[e] = (unsigned char)__ldcg(&g_nbr[(bid * RPB + rw) * N + kk]);
        }
        if (t < RPB) sdeg[t] = __ldcg(&g_deg[bid * RPB + t]);
    }
    CSYNC();

    // ============ 50 MPM iterations, one cluster.sync each ==================
    // F positively homogeneous: exact norm carried as scalar; partials are
    // published in the same release (CSYNC) as the M rows.
    const int gbase = bid * RPB * N;
    const int rg3   = (t / 96) * 3;               // rowgrp base (0,3,6,9)
    for (int it = 0; it < ITERS; it++) {
        const float* __restrict__ Min  = g_M[it & 1];
        float*       __restrict__ Mout = g_M[(it + 1) & 1];

        if (it == 0) { if (t == 0) s_scale = 1.f; }
        else if (wid == 0) {
            float p = (lane < NB) ? __ldcg(&g_part[(it - 1) & 1][lane]) : 0.f;
            #pragma unroll
            for (int o = 4; o; o >>= 1) p += __shfl_xor_sync(~0u, p, o);
            if (lane == 0) s_scale = rsqrtf(p);
        }

        float a[3];
        #pragma unroll
        for (int i2 = 0; i2 < 3; i2++) {
            int e  = t + i2 * NT;
            int rw = row0 + i2 * 4;
            float acc = sX[e] * sND[e];
            int dg = sdeg[rw];
            const unsigned char* nb = &snbr[rw * N];
            for (int m = 0; m < dg; m++)
                acc += __ldcg(&Min[nb[m] * N + kk]);   // ldcg: dbl-buffered, L1 stale
            a[i2] = acc;
        }
        __syncthreads();                    // s_scale ready; old-sX reads done
        float ss = s_scale;
        float sq = 0.f;
        #pragma unroll
        for (int i2 = 0; i2 < 3; i2++) {
            float v = a[i2] * ss;
            sX[t + i2 * NT] = v;
            sq += v * v;
        }
        #pragma unroll
        for (int o = 16; o; o >>= 1) sq += __shfl_xor_sync(~0u, sq, o);
        if (lane == 0) red[wid] = sq;
        __syncthreads();                    // red ready; new sX published
        if (t == 0) {
            float s2 = 0.f;
            #pragma unroll
            for (int w = 0; w < 12; w++) s2 += red[w];
            __stcg(&g_part[it & 1][bid], s2);
        }

        if (it != ITERS - 1) {
            // M[row,k] = max_{l!=k} B[k,l] * x_row[l]; B' in smem, diag zeroed.
            const float* x0 = &sX[(rg3 + 0) * N];
            const float* x1 = &sX[(rg3 + 1) * N];
            const float* x2 = &sX[(rg3 + 2) * N];
            float m0 = 0.f, m1 = 0.f, m2 = 0.f;
            #pragma unroll 8
            for (int l = 0; l < N; l++) {
                float b = dyn[l * N + kk];            // coalesced, conflict-free
                m0 = fmaxf(m0, b * x0[l]);
                m1 = fmaxf(m1, b * x1[l]);
                m2 = fmaxf(m2, b * x2[l]);
            }
            __stcg(&Mout[gbase + (rg3 + 0) * N + kk], m0);
            __stcg(&Mout[gbase + (rg3 + 1) * N + kk], m1);
            __stcg(&Mout[gbase + (rg3 + 2) * N + kk], m2);
        }
        CSYNC();
    }

    // ============ final normalize + write ===================================
    {
        if (wid == 0) {
            float p = (lane < NB) ? __ldcg(&g_part[(ITERS - 1) & 1][lane]) : 0.f;
            #pragma unroll
            for (int o = 4; o; o >>= 1) p += __shfl_xor_sync(~0u, p, o);
            if (lane == 0) s_scale = rsqrtf(p);
        }
        __syncthreads();
        #pragma unroll
        for (int i2 = 0; i2 < 3; i2++)
            out[gbase + t + i2 * NT] = sX[t + i2 * NT] * s_scale;
    }
}

// ---------------- launch ----------------
extern "C" void kernel_launch(void* const* d_in, const int* in_sizes, int n_in,
                              void* d_out, int out_size) {
    const float* x   = (const float*)d_in[0];
    const int*   ei  = (const int*)  d_in[1];
    const float* adj = (const float*)d_in[2];
    const float* W1  = (const float*)d_in[3];
    // d_in[4] = b1 (cancelled by BN)
    const float* g1  = (const float*)d_in[5];
    const float* be1 = (const float*)d_in[6];
    const float* W2  = (const float*)d_in[7];
    // d_in[8] = b2 (cancelled by BN)
    const float* g2  = (const float*)d_in[9];
    const float* be2 = (const float*)d_in[10];
    const float* Wmu = (const float*)d_in[11];
    const float* bmu = (const float*)d_in[12];
    const float* Wlv = (const float*)d_in[13];
    const float* blv = (const float*)d_in[14];
    const float* Wd1 = (const float*)d_in[15];
    const float* bd1 = (const float*)d_in[16];
    const float* Wd2 = (const float*)d_in[17];
    const float* bd2 = (const float*)d_in[18];
    const float* eps = (const float*)d_in[19];

    fused_graphvae<<<NB, NT>>>(
        x, ei, adj, W1, g1, be1, W2, g2, be2,
        Wmu, bmu, Wlv, blv, Wd1, bd1, Wd2, bd2, eps, (float*)d_out);
}